// round 13
// baseline (speedup 1.0000x reference)
#include <cuda_runtime.h>
#include <math_constants.h>

// Morphological opening (10x10 min then 10x10 max, SAME pad lo=4/hi=5),
// NHWC [16,512,512,8] f32. Fused single kernel, vertical-first van Herk.
// Block = 16(h) x 32(w) x 8ch, float4, coalesced gmem, 3 blocks/SM.
// vs round 12: NT=320 so ALL stages are single-round (V1's 300 tasks no
// longer need a mostly-idle second round), 30 warps/SM. Tail batches split
// into 4-wide chunks to fit the 68-reg cap without spills.

#define H_   512
#define W_   512
#define TH   16
#define TW   32
#define NT   320

#define NE    25             // eroded row range (TH + 9)
#define NCB   50             // input cols covered (TW + 18)
#define NCE   41             // eroded cols with dilation halo (TW + 9)

#define BCF   (NCB * 2)      // 100 fused (col,half) B columns
#define ECF   (NCE * 2)      // 82 fused E columns
#define FCF   (TW * 2)       // 64 fused F columns

#define B_OFF 0
#define E_OFF (BCF * NE)                 // 2500
#define F_OFF 0                          // F: 64*25=1600, overlays B
#define SMEM_F4 (E_OFF + ECF * NE + 200) // 4750 (+200 f4 over-read pad)
#define SMEM_BYTES (SMEM_F4 * 16)        // 76,000 -> 3 blocks/SM

__device__ __forceinline__ float4 min4(float4 a, float4 b) {
    return make_float4(fminf(a.x,b.x), fminf(a.y,b.y), fminf(a.z,b.z), fminf(a.w,b.w));
}
__device__ __forceinline__ float4 max4(float4 a, float4 b) {
    return make_float4(fmaxf(a.x,b.x), fmaxf(a.y,b.y), fmaxf(a.z,b.z), fmaxf(a.w,b.w));
}

__global__ __launch_bounds__(NT, 3)
void opening_kernel(const float4* __restrict__ in4, float4* __restrict__ out4) {
    extern __shared__ float4 sm[];
    float4* Bs = sm + B_OFF;   // B[cF][e], cF = cb*2 + h
    float4* Es = sm + E_OFF;   // E[cF'][e]
    float4* Fs = sm + F_OFF;   // F[cF''][e]

    const int b   = blockIdx.z;
    const int gh0 = blockIdx.y * TH;
    const int gw0 = blockIdx.x * TW;
    const int tid = threadIdx.x;

    const size_t chanBase = (size_t)b * H_ * W_ * 2;   // f4 units
    const float4 INF4  = make_float4( CUDART_INF_F,  CUDART_INF_F,  CUDART_INF_F,  CUDART_INF_F);
    const float4 NINF4 = make_float4(-CUDART_INF_F, -CUDART_INF_F, -CUDART_INF_F, -CUDART_INF_F);

    // ---- V1: vertical min fused with coalesced gmem load. 300 tasks (1 round). ----
    if (tid < BCF * 3) {
        int cF  = tid % BCF, seg = tid / BCF;
        int e0  = seg * 9;
        int n   = (seg == 2) ? 7 : 9;           // 9+9+7 = 25
        int gx  = gw0 + (cF >> 1) - 8;
        int yBase = gh0 - 8 + e0;
        float4* q = Bs + cF * NE + e0;

        if ((unsigned)gx >= W_) {
            #pragma unroll
            for (int j = 0; j < 9; j++) if (j < n) q[j] = INF4;
        } else {
            const float4* src = in4 + chanBase + (size_t)gx * 2 + (cF & 1);
            float4 x[10], y0[4], y1[4];
            if (yBase >= 0 && yBase <= H_ - 18) {
                #pragma unroll
                for (int t = 0; t < 10; t++) x[t]  = src[(size_t)(yBase + t)      * (W_ * 2)];
                #pragma unroll
                for (int t = 0; t < 4;  t++) y0[t] = src[(size_t)(yBase + 10 + t) * (W_ * 2)];
            } else {
                #pragma unroll
                for (int t = 0; t < 10; t++) {
                    int gy = yBase + t;  x[t] = INF4;
                    if ((unsigned)gy < H_) x[t] = src[(size_t)gy * (W_ * 2)];
                }
                #pragma unroll
                for (int t = 0; t < 4; t++) {
                    int gy = yBase + 10 + t;  y0[t] = INF4;
                    if ((unsigned)gy < H_) y0[t] = src[(size_t)gy * (W_ * 2)];
                }
            }
            #pragma unroll
            for (int j = 8; j >= 0; j--) x[j] = min4(x[j], x[j+1]);
            float4 pr = x[9];
            q[0] = x[0];
            #pragma unroll
            for (int j = 1; j <= 4; j++) {
                pr = min4(pr, y0[j - 1]);
                if (j < n) q[j] = min4(x[j], pr);
            }
            if (yBase >= 0 && yBase <= H_ - 18) {
                #pragma unroll
                for (int t = 0; t < 4; t++) y1[t] = src[(size_t)(yBase + 14 + t) * (W_ * 2)];
            } else {
                #pragma unroll
                for (int t = 0; t < 4; t++) {
                    int gy = yBase + 14 + t;  y1[t] = INF4;
                    if ((unsigned)gy < H_) y1[t] = src[(size_t)gy * (W_ * 2)];
                }
            }
            #pragma unroll
            for (int j = 5; j <= 8; j++) {
                pr = min4(pr, y1[j - 5]);
                if (j < n) q[j] = min4(x[j], pr);
            }
        }
    }
    __syncthreads();

    // ---- H1: horizontal min B -> eroded E, mask -inf off-image. 250 tasks. ----
    if (tid < 25 * 2 * 5) {
        int e   = tid % NE;
        int t2  = tid / NE;        // 0..9
        int h   = t2 & 1;
        int seg = t2 >> 1;         // 0..4
        int c0  = seg * 9;
        int n   = (seg == 4) ? 5 : 9;          // 41 outputs
        const float4* row = Bs + h * NE + e;   // col cb at offset cb*2*NE
        float4 x[10];
        #pragma unroll
        for (int t = 0; t < 10; t++) x[t] = row[(c0 + t) * (2 * NE)];
        #pragma unroll
        for (int j = 8; j >= 0; j--) x[j] = min4(x[j], x[j+1]);
        float4 y[4];
        #pragma unroll
        for (int t = 0; t < 4; t++) y[t] = row[(c0 + 10 + t) * (2 * NE)]; // over-read safe
        float4 pr = x[9];
        bool rowOK = ((unsigned)(gh0 + e - 4) < H_);
        float4* q = Es + (c0 * 2 + h) * NE + e;
        q[0] = (rowOK && (unsigned)(gw0 + c0 - 4) < W_) ? x[0] : NINF4;
        #pragma unroll
        for (int j = 1; j <= 4; j++) {
            pr = min4(pr, y[j - 1]);
            if (j < n) {
                float4 v = min4(x[j], pr);
                if (!rowOK || (unsigned)(gw0 + c0 + j - 4) >= W_) v = NINF4;
                q[j * (2 * NE)] = v;
            }
        }
        #pragma unroll
        for (int t = 0; t < 4; t++) y[t] = row[(c0 + 14 + t) * (2 * NE)];
        #pragma unroll
        for (int j = 5; j <= 8; j++) {
            pr = min4(pr, y[j - 5]);
            if (j < n) {
                float4 v = min4(x[j], pr);
                if (!rowOK || (unsigned)(gw0 + c0 + j - 4) >= W_) v = NINF4;
                q[j * (2 * NE)] = v;
            }
        }
    }
    __syncthreads();

    // ---- H2: horizontal max E -> F. 200 tasks. ----
    if (tid < 25 * 2 * 4) {
        int e   = tid % NE;
        int t2  = tid / NE;        // 0..7
        int h   = t2 & 1;
        int seg = t2 >> 1;         // 0..3
        int c0  = seg * 9;
        int n   = (seg == 3) ? 5 : 9;          // 32 outputs
        const float4* row = Es + h * NE + e;
        float4 x[10];
        #pragma unroll
        for (int t = 0; t < 10; t++) x[t] = row[(c0 + t) * (2 * NE)];
        #pragma unroll
        for (int j = 8; j >= 0; j--) x[j] = max4(x[j], x[j+1]);
        float4 y[4];
        #pragma unroll
        for (int t = 0; t < 4; t++) y[t] = row[(c0 + 10 + t) * (2 * NE)]; // over-read safe
        float4 pr = x[9];
        float4* q = Fs + (c0 * 2 + h) * NE + e;
        q[0] = x[0];
        #pragma unroll
        for (int j = 1; j <= 4; j++) {
            pr = max4(pr, y[j - 1]);
            if (j < n) q[j * (2 * NE)] = max4(x[j], pr);
        }
        #pragma unroll
        for (int t = 0; t < 4; t++) y[t] = row[(c0 + 14 + t) * (2 * NE)];
        #pragma unroll
        for (int j = 5; j <= 8; j++) {
            pr = max4(pr, y[j - 5]);
            if (j < n) q[j * (2 * NE)] = max4(x[j], pr);
        }
    }
    __syncthreads();

    // ---- V2: vertical max F -> gmem (coalesced). 128 tasks. ----
    if (tid < FCF * 2) {
        int cF  = tid % FCF, seg = tid / FCF;
        int r0  = seg * 9;
        int n   = (seg == 1) ? 7 : 9;          // 16 outputs
        const float4* p = Fs + cF * NE + r0;   // stride 1 along e
        float4 x[10];
        #pragma unroll
        for (int t = 0; t < 10; t++) x[t] = p[t];
        #pragma unroll
        for (int j = 8; j >= 0; j--) x[j] = max4(x[j], x[j+1]);
        float4 y[4];
        #pragma unroll
        for (int t = 0; t < 4; t++) y[t] = p[10 + t];   // over-read safe
        float4 pr = x[9];
        float4* q = out4 + chanBase + ((size_t)(gh0 + r0) * W_ + gw0) * 2 + cF;
        q[0] = x[0];
        #pragma unroll
        for (int j = 1; j <= 4; j++) {
            pr = max4(pr, y[j - 1]);
            if (j < n) q[(size_t)j * (W_ * 2)] = max4(x[j], pr);
        }
        #pragma unroll
        for (int t = 0; t < 4; t++) y[t] = p[14 + t];
        #pragma unroll
        for (int j = 5; j <= 8; j++) {
            pr = max4(pr, y[j - 5]);
            if (j < n) q[(size_t)j * (W_ * 2)] = max4(x[j], pr);
        }
    }
}

extern "C" void kernel_launch(void* const* d_in, const int* in_sizes, int n_in,
                              void* d_out, int out_size) {
    const float4* in  = (const float4*)d_in[0];
    float4* out = (float4*)d_out;

    cudaFuncSetAttribute(opening_kernel,
                         cudaFuncAttributeMaxDynamicSharedMemorySize, SMEM_BYTES);

    dim3 grid(W_ / TW, H_ / TH, 16);
    opening_kernel<<<grid, NT, SMEM_BYTES>>>(in, out);
}

// round 14
// speedup vs baseline: 1.3372x; 1.3372x over previous
#include <cuda_runtime.h>
#include <math_constants.h>

// Morphological opening (10x10 min then 10x10 max, SAME pad lo=4/hi=5),
// NHWC [16,512,512,8] f32. Fused kernel, vertical-first, STREAMING van Herk
// (Gil-Werman): every element is loaded exactly once per stage (segmented
// version re-read ~2x). float2 granularity keeps live state (~19 f2) under
// the 84-reg/3-block cap. Block = 16(h) x 32(w) x 8ch, 3 blocks/SM.
// Boundary masking is hoisted to whole-task uniform branches.

#define H_  512
#define W_  512
#define TH  16
#define TW  32
#define NT  256

#define NE  25            // outputs per column (TH + 9)
#define NCB 50            // B cols (TW + 18)
#define NCE 41            // E cols (TW + 9)
#define BQ  (NCB * 4)     // 200 fused (col, f2-quarter) B columns
#define EQ  (NCE * 4)     // 164
#define FQ  (TW * 4)      // 128

#define E_OFF (BQ * NE)                 // 5000 f2
#define SMEM_F2 (E_OFF + EQ * NE)       // 9100 f2
#define SMEM_BYTES (SMEM_F2 * 8)        // 72,800 -> 3 blocks/SM

__device__ __forceinline__ float2 mn2(float2 a, float2 b) {
    return make_float2(fminf(a.x,b.x), fminf(a.y,b.y));
}
__device__ __forceinline__ float2 mx2(float2 a, float2 b) {
    return make_float2(fmaxf(a.x,b.x), fmaxf(a.y,b.y));
}
template<bool MN>
__device__ __forceinline__ float2 op2(float2 a, float2 b) { return MN ? mn2(a,b) : mx2(a,b); }

// Streaming van Herk: out[i] = OP(in[i..i+9]) for i in [0,NOUT).
// Reads in[0..NOUT+8] exactly once via ld(t); emits via st(i,v).
template<bool MN, int NOUT, class L, class S>
__device__ __forceinline__ void svh(L ld, S st) {
    constexpr int NIN  = NOUT + 9;
    constexpr int NBLK = (NOUT + 8) / 9;
    float2 s[9];
    #pragma unroll
    for (int t = 0; t < 9; t++) s[t] = ld(t);
    #pragma unroll
    for (int j = 7; j >= 0; j--) s[j] = op2<MN>(s[j], s[j+1]);
    #pragma unroll
    for (int m = 0; m < NBLK; m++) {
        const int base = 9 * m;
        const int ycnt = (NIN - 9*(m+1) < 9) ? (NIN - 9*(m+1)) : 9;
        float2 y[9];
        #pragma unroll
        for (int t = 0; t < 9; t++) if (t < ycnt) y[t] = ld(9*(m+1) + t);
        float2 pr = y[0];
        st(base, op2<MN>(s[0], pr));
        #pragma unroll
        for (int r = 1; r < 9; r++) {
            if (base + r < NOUT) {
                pr = op2<MN>(pr, y[r]);
                st(base + r, op2<MN>(s[r], pr));
            }
        }
        if (m + 1 < NBLK) {   // only the final block is ever partial
            #pragma unroll
            for (int j = 7; j >= 0; j--) y[j] = op2<MN>(y[j], y[j+1]);
            #pragma unroll
            for (int t = 0; t < 9; t++) s[t] = y[t];
        }
    }
}

__global__ __launch_bounds__(NT, 3)
void opening_kernel(const float2* __restrict__ in2, float2* __restrict__ out2) {
    extern __shared__ float2 sm[];
    float2* Bs = sm;            // B[cQ][e], cQ = cb*4 + q, stride NE
    float2* Es = sm + E_OFF;    // E[cQ'][e]
    float2* Fs = sm;            // F[cQ''][e], overlays B (3200 <= 5000)

    const int b   = blockIdx.z;
    const int gh0 = blockIdx.y * TH;
    const int gw0 = blockIdx.x * TW;
    const int tid = threadIdx.x;

    const size_t chanBase = (size_t)b * ((size_t)H_ * W_ * 4);  // f2 units
    const float2 INF2  = make_float2( CUDART_INF_F,  CUDART_INF_F);
    const float2 NINF2 = make_float2(-CUDART_INF_F, -CUDART_INF_F);

    // ---- V1: vertical min streamed from gmem (coalesced). 200 tasks. ----
    // B[cQ][e] = min input rows (gh0-8+e .. gh0+1+e), x = gw0 + (cQ>>2) - 8.
    if (tid < BQ) {
        int cQ = tid, cb = cQ >> 2, q = cQ & 3;
        int gx = gw0 + cb - 8;
        float2* qB = Bs + cQ * NE;
        if ((unsigned)gx >= W_) {
            #pragma unroll
            for (int i = 0; i < NE; i++) qB[i] = INF2;
        } else {
            const float2* src = in2 + chanBase + (size_t)gx * 4 + q;
            int gy0 = gh0 - 8;
            auto st = [&](int i, float2 v) { qB[i] = v; };
            if (gh0 != 0 && gh0 != (H_ - TH)) {      // rows gh0-8..gh0+25 all valid
                auto ld = [&](int t) { return src[(size_t)(gy0 + t) * (W_ * 4)]; };
                svh<true, NE>(ld, st);
            } else {
                auto ld = [&](int t) {
                    int gy = gy0 + t; float2 v = INF2;
                    if ((unsigned)gy < H_) v = src[(size_t)gy * (W_ * 4)];
                    return v;
                };
                svh<true, NE>(ld, st);
            }
        }
    }
    __syncthreads();

    // ---- H1: horizontal min B -> E, mask -inf off-image. 200 tasks. ----
    // Task = (half, q, e); halfA: c' 0..20 (21 out), halfB: c' 21..40 (20 out).
    if (tid < 200) {
        int e = tid % 25, t2 = tid / 25;
        int q = t2 & 3, half = t2 >> 2;
        bool rowOK = ((unsigned)(gh0 + e - 4) < H_);
        bool inter = rowOK && (gw0 != 0) && (gw0 != (W_ - TW));
        if (half == 0) {
            const float2* pB = Bs + q * NE + e;               // + cb*(4*NE)
            float2*       pE = Es + q * NE + e;
            auto ld = [&](int t) { return pB[t * (4 * NE)]; };
            if (inter) {
                auto st = [&](int i, float2 v) { pE[i * (4 * NE)] = v; };
                svh<true, 21>(ld, st);
            } else {
                auto st = [&](int i, float2 v) {
                    bool ok = rowOK && ((unsigned)(gw0 + i - 4) < W_);
                    pE[i * (4 * NE)] = ok ? v : NINF2;
                };
                svh<true, 21>(ld, st);
            }
        } else {
            const float2* pB = Bs + (21 * 4 + q) * NE + e;
            float2*       pE = Es + (21 * 4 + q) * NE + e;
            auto ld = [&](int t) { return pB[t * (4 * NE)]; };
            if (inter) {
                auto st = [&](int i, float2 v) { pE[i * (4 * NE)] = v; };
                svh<true, 20>(ld, st);
            } else {
                auto st = [&](int i, float2 v) {
                    bool ok = rowOK && ((unsigned)(gw0 + 21 + i - 4) < W_);
                    pE[i * (4 * NE)] = ok ? v : NINF2;
                };
                svh<true, 20>(ld, st);
            }
        }
    }
    __syncthreads();

    // ---- H2: horizontal max E -> F. 200 tasks; halves of 16 outputs. ----
    if (tid < 200) {
        int e = tid % 25, t2 = tid / 25;
        int q = t2 & 3, half = t2 >> 2;
        int c0 = half * 16;
        const float2* pE = Es + (c0 * 4 + q) * NE + e;
        float2*       pF = Fs + (c0 * 4 + q) * NE + e;
        auto ld = [&](int t) { return pE[t * (4 * NE)]; };
        auto st = [&](int i, float2 v) { pF[i * (4 * NE)] = v; };
        svh<false, 16>(ld, st);
    }
    __syncthreads();

    // ---- V2: vertical max F -> gmem (coalesced). 128 tasks. ----
    if (tid < FQ) {
        const float2* pF = Fs + tid * NE;    // stride 1 along e
        float2* qo = out2 + chanBase + ((size_t)gh0 * W_ + gw0) * 4 + tid;
        auto ld = [&](int t) { return pF[t]; };
        auto st = [&](int i, float2 v) { qo[(size_t)i * (W_ * 4)] = v; };
        svh<false, TH>(ld, st);
    }
}

extern "C" void kernel_launch(void* const* d_in, const int* in_sizes, int n_in,
                              void* d_out, int out_size) {
    const float2* in  = (const float2*)d_in[0];
    float2* out = (float2*)d_out;

    cudaFuncSetAttribute(opening_kernel,
                         cudaFuncAttributeMaxDynamicSharedMemorySize, SMEM_BYTES);

    dim3 grid(W_ / TW, H_ / TH, 16);
    opening_kernel<<<grid, NT, SMEM_BYTES>>>(in, out);
}

// round 15
// speedup vs baseline: 1.7656x; 1.3203x over previous
#include <cuda_runtime.h>
#include <math_constants.h>

// Morphological opening (10x10 min then 10x10 max, SAME pad lo=4/hi=5),
// NHWC [16,512,512,8] f32. Fused kernel, vertical-first, streaming van Herk.
// vs round 14: H-min and H-max are CHAINED IN REGISTERS (producer/consumer
// streaming van Herk) -- the eroded intermediate E never touches smem, and
// one barrier disappears. Stages: V1 gmem->B, Hfused B->F, V2 F->gmem.
// Block = 16(h) x 32(w) x 8ch, float2 granularity, 65.6KB smem, 3 blocks/SM.

#define H_  512
#define W_  512
#define TH  16
#define TW  32
#define NT  256

#define NE  25            // outputs per column (TH + 9)
#define NCB 50            // B cols (TW + 18)
#define BQ  (NCB * 4)     // 200 fused (col, f2-quarter) B columns
#define FQ  (TW * 4)      // 128

#define F_OFF (BQ * NE)               // 5000 f2
#define SMEM_F2 (F_OFF + FQ * NE)     // 8200 f2
#define SMEM_BYTES (SMEM_F2 * 8)      // 65,600 -> 3 blocks/SM

__device__ __forceinline__ float2 mn2(float2 a, float2 b) {
    return make_float2(fminf(a.x,b.x), fminf(a.y,b.y));
}
__device__ __forceinline__ float2 mx2(float2 a, float2 b) {
    return make_float2(fmaxf(a.x,b.x), fmaxf(a.y,b.y));
}
template<bool MN>
__device__ __forceinline__ float2 op2(float2 a, float2 b) { return MN ? mn2(a,b) : mx2(a,b); }

// Streaming van Herk: out[i] = OP(in[i..i+9]) for i in [0,NOUT).
template<bool MN, int NOUT, class L, class S>
__device__ __forceinline__ void svh(L ld, S st) {
    constexpr int NIN  = NOUT + 9;
    constexpr int NBLK = (NOUT + 8) / 9;
    float2 s[9];
    #pragma unroll
    for (int t = 0; t < 9; t++) s[t] = ld(t);
    #pragma unroll
    for (int j = 7; j >= 0; j--) s[j] = op2<MN>(s[j], s[j+1]);
    #pragma unroll
    for (int m = 0; m < NBLK; m++) {
        const int base = 9 * m;
        const int ycnt = (NIN - 9*(m+1) < 9) ? (NIN - 9*(m+1)) : 9;
        float2 y[9];
        #pragma unroll
        for (int t = 0; t < 9; t++) if (t < ycnt) y[t] = ld(9*(m+1) + t);
        float2 pr = y[0];
        st(base, op2<MN>(s[0], pr));
        #pragma unroll
        for (int r = 1; r < 9; r++) {
            if (base + r < NOUT) {
                pr = op2<MN>(pr, y[r]);
                st(base + r, op2<MN>(s[r], pr));
            }
        }
        if (m + 1 < NBLK) {
            #pragma unroll
            for (int j = 7; j >= 0; j--) y[j] = op2<MN>(y[j], y[j+1]);
            #pragma unroll
            for (int t = 0; t < 9; t++) s[t] = y[t];
        }
    }
}

__global__ __launch_bounds__(NT, 3)
void opening_kernel(const float2* __restrict__ in2, float2* __restrict__ out2) {
    extern __shared__ float2 sm[];
    float2* Bs = sm;            // B[cQ][e], cQ = cb*4 + q, stride NE
    float2* Fs = sm + F_OFF;    // F[cQ''][e]

    const int b   = blockIdx.z;
    const int gh0 = blockIdx.y * TH;
    const int gw0 = blockIdx.x * TW;
    const int tid = threadIdx.x;

    const size_t chanBase = (size_t)b * ((size_t)H_ * W_ * 4);  // f2 units
    const float2 INF2  = make_float2( CUDART_INF_F,  CUDART_INF_F);
    const float2 NINF2 = make_float2(-CUDART_INF_F, -CUDART_INF_F);

    // ---- V1: vertical min streamed from gmem (coalesced). 200 tasks. ----
    if (tid < BQ) {
        int cQ = tid, cb = cQ >> 2, q = cQ & 3;
        int gx = gw0 + cb - 8;
        float2* qB = Bs + cQ * NE;
        if ((unsigned)gx >= W_) {
            #pragma unroll
            for (int i = 0; i < NE; i++) qB[i] = INF2;
        } else {
            const float2* src = in2 + chanBase + (size_t)gx * 4 + q;
            int gy0 = gh0 - 8;
            auto st = [&](int i, float2 v) { qB[i] = v; };
            if (gh0 != 0 && gh0 != (H_ - TH)) {
                auto ld = [&](int t) { return src[(size_t)(gy0 + t) * (W_ * 4)]; };
                svh<true, NE>(ld, st);
            } else {
                auto ld = [&](int t) {
                    int gy = gy0 + t; float2 v = INF2;
                    if ((unsigned)gy < H_) v = src[(size_t)gy * (W_ * 4)];
                    return v;
                };
                svh<true, NE>(ld, st);
            }
        }
    }
    __syncthreads();

    // ---- Hfused: B -> F, eroded E chained in registers. 200 tasks. ----
    // Task (half,q,e): F[j] (16 outputs, j local) at cols gw0 + half*16 + j.
    // E[i] = min(B[i..i+9]) (local, offset half*16), F[j] = max(E[j..j+9]).
    if (tid < 200) {
        int e    = tid % 25;
        int t2   = tid / 25;       // 0..7
        int q    = t2 & 3;
        int half = t2 >> 2;
        int cB0  = half * 16;
        const float2* pB = Bs + (cB0 * 4 + q) * NE + e;  // B col step 4*NE
        float2*       pF = Fs + (cB0 * 4 + q) * NE + e;  // F col = cB0 + j
        bool rowOK   = ((unsigned)(gh0 + e - 4) < H_);
        int  colBase = gw0 + cB0 - 4;                    // E i=0 global col
        bool needMask = !(rowOK && colBase >= 0 && colBase + 24 < W_);

        float2 sB[9], yB[9], sE[9], eb[9];
        // producer init: sB = suffix_min(B[0..8])
        #pragma unroll
        for (int t = 0; t < 9; t++) sB[t] = pB[t * (4 * NE)];
        #pragma unroll
        for (int j = 7; j >= 0; j--) sB[j] = mn2(sB[j], sB[j+1]);

        // --- produce E[0..8] ---
        #pragma unroll
        for (int t = 0; t < 9; t++) yB[t] = pB[(9 + t) * (4 * NE)];
        {
            float2 pr = yB[0];
            eb[0] = mn2(sB[0], pr);
            #pragma unroll
            for (int r = 1; r < 9; r++) { pr = mn2(pr, yB[r]); eb[r] = mn2(sB[r], pr); }
        }
        if (needMask) {
            #pragma unroll
            for (int r = 0; r < 9; r++)
                if (!rowOK || (unsigned)(colBase + r) >= W_) eb[r] = NINF2;
        }
        // consumer init: sE = suffix_max(E[0..8])
        #pragma unroll
        for (int t = 0; t < 9; t++) sE[t] = eb[t];
        #pragma unroll
        for (int j = 7; j >= 0; j--) sE[j] = mx2(sE[j], sE[j+1]);
        // producer: sB = suffix_min(B[9..17])
        #pragma unroll
        for (int j = 7; j >= 0; j--) yB[j] = mn2(yB[j], yB[j+1]);
        #pragma unroll
        for (int t = 0; t < 9; t++) sB[t] = yB[t];

        // --- produce E[9..17], emit F[0..8] ---
        #pragma unroll
        for (int t = 0; t < 9; t++) yB[t] = pB[(18 + t) * (4 * NE)];
        {
            float2 pr = yB[0];
            eb[0] = mn2(sB[0], pr);
            #pragma unroll
            for (int r = 1; r < 9; r++) { pr = mn2(pr, yB[r]); eb[r] = mn2(sB[r], pr); }
        }
        if (needMask) {
            #pragma unroll
            for (int r = 0; r < 9; r++)
                if (!rowOK || (unsigned)(colBase + 9 + r) >= W_) eb[r] = NINF2;
        }
        {
            float2 pr = eb[0];
            pF[0] = mx2(sE[0], pr);
            #pragma unroll
            for (int r = 1; r < 9; r++) { pr = mx2(pr, eb[r]); pF[r * (4 * NE)] = mx2(sE[r], pr); }
        }
        // consumer: sE = suffix_max(E[9..17])
        #pragma unroll
        for (int j = 7; j >= 0; j--) eb[j] = mx2(eb[j], eb[j+1]);
        #pragma unroll
        for (int t = 0; t < 9; t++) sE[t] = eb[t];
        // producer: sB = suffix_min(B[18..26])
        #pragma unroll
        for (int j = 7; j >= 0; j--) yB[j] = mn2(yB[j], yB[j+1]);
        #pragma unroll
        for (int t = 0; t < 9; t++) sB[t] = yB[t];

        // --- produce E[18..24] (7), emit F[9..15] (7) ---
        #pragma unroll
        for (int t = 0; t < 7; t++) yB[t] = pB[(27 + t) * (4 * NE)];
        {
            float2 pr = yB[0];
            eb[0] = mn2(sB[0], pr);
            #pragma unroll
            for (int r = 1; r < 7; r++) { pr = mn2(pr, yB[r]); eb[r] = mn2(sB[r], pr); }
        }
        if (needMask) {
            #pragma unroll
            for (int r = 0; r < 7; r++)
                if (!rowOK || (unsigned)(colBase + 18 + r) >= W_) eb[r] = NINF2;
        }
        {
            float2 pr = eb[0];
            pF[9 * (4 * NE)] = mx2(sE[0], pr);
            #pragma unroll
            for (int r = 1; r < 7; r++) { pr = mx2(pr, eb[r]); pF[(9 + r) * (4 * NE)] = mx2(sE[r], pr); }
        }
    }
    __syncthreads();

    // ---- V2: vertical max F -> gmem (coalesced). 128 tasks. ----
    if (tid < FQ) {
        const float2* pF = Fs + tid * NE;    // stride 1 along e
        float2* qo = out2 + chanBase + ((size_t)gh0 * W_ + gw0) * 4 + tid;
        auto ld = [&](int t) { return pF[t]; };
        auto st = [&](int i, float2 v) { qo[(size_t)i * (W_ * 4)] = v; };
        svh<false, TH>(ld, st);
    }
}

extern "C" void kernel_launch(void* const* d_in, const int* in_sizes, int n_in,
                              void* d_out, int out_size) {
    const float2* in  = (const float2*)d_in[0];
    float2* out = (float2*)d_out;

    cudaFuncSetAttribute(opening_kernel,
                         cudaFuncAttributeMaxDynamicSharedMemorySize, SMEM_BYTES);

    dim3 grid(W_ / TW, H_ / TH, 16);
    opening_kernel<<<grid, NT, SMEM_BYTES>>>(in, out);
}